// round 1
// baseline (speedup 1.0000x reference)
#include <cuda_runtime.h>
#include <cuda_bf16.h>
#include <math.h>

// Problem constants
#define BATCH   2
#define SEQ     2048
#define DMODEL  1024
#define NHEAD   16
#define DK      64
#define MROWS   (BATCH * SEQ)      // 4096

// ---------------------------------------------------------------------------
// Scratch (allocation-free rule: __device__ globals)
// ---------------------------------------------------------------------------
__device__ float g_Q[MROWS * DMODEL];
__device__ float g_K[MROWS * DMODEL];
__device__ float g_V[MROWS * DMODEL];
__device__ float g_O[MROWS * DMODEL];

// ---------------------------------------------------------------------------
// GEMM: C[M,N] = A[M,K] @ W[N,K]^T + bias[N]
// 128x128 tile, BK=8, 256 threads, 8x8 micro-tile per thread.
// M=4096, N=1024, K=1024 (exact multiples; no bounds checks).
// ---------------------------------------------------------------------------
#define GBM 128
#define GBN 128
#define GBK 8
#define GPAD 132

__global__ __launch_bounds__(256)
void gemm_bias_kernel(const float* __restrict__ A,
                      const float* __restrict__ W,
                      const float* __restrict__ bias,
                      float* __restrict__ C,
                      int M, int N, int K)
{
    __shared__ float As[GBK][GPAD];
    __shared__ float Ws[GBK][GPAD];

    const int tid = threadIdx.x;
    const int ty  = tid >> 4;        // 0..15 -> output row group
    const int tx  = tid & 15;        // 0..15 -> output col group
    const int row0 = blockIdx.y * GBM;
    const int col0 = blockIdx.x * GBN;

    // Load mapping: each thread loads one float4 of A and one of W per k-tile
    const int lr = tid >> 1;          // 0..127
    const int lc = (tid & 1) * 4;     // 0 or 4

    const float* Aptr = A + (size_t)(row0 + lr) * K + lc;
    const float* Wptr = W + (size_t)(col0 + lr) * K + lc;

    float acc[8][8];
#pragma unroll
    for (int i = 0; i < 8; i++)
#pragma unroll
        for (int j = 0; j < 8; j++) acc[i][j] = 0.f;

    for (int kt = 0; kt < K; kt += GBK) {
        float4 av = *(const float4*)(Aptr + kt);
        float4 wv = *(const float4*)(Wptr + kt);
        As[lc + 0][lr] = av.x;
        As[lc + 1][lr] = av.y;
        As[lc + 2][lr] = av.z;
        As[lc + 3][lr] = av.w;
        Ws[lc + 0][lr] = wv.x;
        Ws[lc + 1][lr] = wv.y;
        Ws[lc + 2][lr] = wv.z;
        Ws[lc + 3][lr] = wv.w;
        __syncthreads();

#pragma unroll
        for (int k = 0; k < GBK; k++) {
            float4 a0 = *(const float4*)&As[k][ty * 8 + 0];
            float4 a1 = *(const float4*)&As[k][ty * 8 + 4];
            float4 w0 = *(const float4*)&Ws[k][tx * 8 + 0];
            float4 w1 = *(const float4*)&Ws[k][tx * 8 + 4];
            float a[8] = {a0.x, a0.y, a0.z, a0.w, a1.x, a1.y, a1.z, a1.w};
            float w[8] = {w0.x, w0.y, w0.z, w0.w, w1.x, w1.y, w1.z, w1.w};
#pragma unroll
            for (int i = 0; i < 8; i++)
#pragma unroll
                for (int j = 0; j < 8; j++)
                    acc[i][j] += a[i] * w[j];
        }
        __syncthreads();
    }

    // bias
    float4 b0 = *(const float4*)(bias + col0 + tx * 8 + 0);
    float4 b1 = *(const float4*)(bias + col0 + tx * 8 + 4);
    float bv[8] = {b0.x, b0.y, b0.z, b0.w, b1.x, b1.y, b1.z, b1.w};

#pragma unroll
    for (int i = 0; i < 8; i++) {
        float* crow = C + (size_t)(row0 + ty * 8 + i) * N + col0 + tx * 8;
        float4 o0 = make_float4(acc[i][0] + bv[0], acc[i][1] + bv[1],
                                acc[i][2] + bv[2], acc[i][3] + bv[3]);
        float4 o1 = make_float4(acc[i][4] + bv[4], acc[i][5] + bv[5],
                                acc[i][6] + bv[6], acc[i][7] + bv[7]);
        *(float4*)(crow + 0) = o0;
        *(float4*)(crow + 4) = o1;
    }
}

// ---------------------------------------------------------------------------
// Flash attention: per block = one (b,h) and 64 query rows.
// BQ=64, BK=64, dk=64. 256 threads as 16x16; each thread owns a 4x4 score
// sub-tile and a 4(row)x4(dcol) output accumulator.
// Online softmax; masked scores set to exactly -1e9 (matches reference).
// ---------------------------------------------------------------------------
#define BQ 64
#define BKT 64
#define ASTR 68   // padded smem stride (floats), keeps 16B alignment

__global__ __launch_bounds__(256)
void attn_kernel(const float* __restrict__ Q, const float* __restrict__ K,
                 const float* __restrict__ V, const int* __restrict__ mask,
                 float* __restrict__ O)
{
    extern __shared__ float sm[];
    float* Qs  = sm;                   // [BQ][ASTR]
    float* KPs = sm + BQ * ASTR;       // K tile, then reused for P
    float* Vs  = sm + 2 * BQ * ASTR;   // [BKT][ASTR]

    const int bh = blockIdx.y;
    const int b  = bh >> 4;
    const int h  = bh & 15;
    const int q0 = blockIdx.x * BQ;
    const int tid = threadIdx.x;
    const int ty = tid >> 4;   // 0..15
    const int tx = tid & 15;   // 0..15

    const float* Qbase = Q + (size_t)b * SEQ * DMODEL + h * DK;
    const float* Kbase = K + (size_t)b * SEQ * DMODEL + h * DK;
    const float* Vbase = V + (size_t)b * SEQ * DMODEL + h * DK;
    const int*   Mbase = mask + (size_t)b * SEQ * SEQ;

    // Load Q tile (64 x 64) -> Qs
    for (int t = tid; t < BQ * 16; t += 256) {
        int r = t >> 4, c4 = (t & 15) * 4;
        *(float4*)(&Qs[r * ASTR + c4]) =
            *(const float4*)(Qbase + (size_t)(q0 + r) * DMODEL + c4);
    }

    float m_i[4], l_i[4], acc[4][4];
#pragma unroll
    for (int i = 0; i < 4; i++) {
        m_i[i] = -INFINITY;
        l_i[i] = 0.f;
#pragma unroll
        for (int j = 0; j < 4; j++) acc[i][j] = 0.f;
    }
    __syncthreads();

    const float scale = 1.0f / 32.0f;   // 1/sqrt(1024)

    for (int kt = 0; kt < SEQ / BKT; kt++) {
        const int k0 = kt * BKT;

        // Load K and V tiles
        for (int t = tid; t < BKT * 16; t += 256) {
            int r = t >> 4, c4 = (t & 15) * 4;
            *(float4*)(&KPs[r * ASTR + c4]) =
                *(const float4*)(Kbase + (size_t)(k0 + r) * DMODEL + c4);
            *(float4*)(&Vs[r * ASTR + c4]) =
                *(const float4*)(Vbase + (size_t)(k0 + r) * DMODEL + c4);
        }
        __syncthreads();

        // Scores: s[i][j] = Q[ty*4+i] . K[tx*4+j]
        float s[4][4];
#pragma unroll
        for (int i = 0; i < 4; i++)
#pragma unroll
            for (int j = 0; j < 4; j++) s[i][j] = 0.f;

#pragma unroll
        for (int d = 0; d < DK; d += 4) {
            float4 qv[4], kv[4];
#pragma unroll
            for (int i = 0; i < 4; i++)
                qv[i] = *(const float4*)&Qs[(ty * 4 + i) * ASTR + d];
#pragma unroll
            for (int j = 0; j < 4; j++)
                kv[j] = *(const float4*)&KPs[(tx * 4 + j) * ASTR + d];
#pragma unroll
            for (int i = 0; i < 4; i++)
#pragma unroll
                for (int j = 0; j < 4; j++) {
                    s[i][j] += qv[i].x * kv[j].x;
                    s[i][j] += qv[i].y * kv[j].y;
                    s[i][j] += qv[i].z * kv[j].z;
                    s[i][j] += qv[i].w * kv[j].w;
                }
        }

        // Mask + scale
#pragma unroll
        for (int i = 0; i < 4; i++) {
            const int* mrow = Mbase + (size_t)(q0 + ty * 4 + i) * SEQ + k0 + tx * 4;
#pragma unroll
            for (int j = 0; j < 4; j++) {
                int mv = mrow[j];
                s[i][j] = (mv != 0) ? s[i][j] * scale : -1e9f;
            }
        }

        // Online softmax per row (row owned by 16 lanes sharing ty)
#pragma unroll
        for (int i = 0; i < 4; i++) {
            float tm = fmaxf(fmaxf(s[i][0], s[i][1]), fmaxf(s[i][2], s[i][3]));
            tm = fmaxf(tm, __shfl_xor_sync(0xffffffffu, tm, 1));
            tm = fmaxf(tm, __shfl_xor_sync(0xffffffffu, tm, 2));
            tm = fmaxf(tm, __shfl_xor_sync(0xffffffffu, tm, 4));
            tm = fmaxf(tm, __shfl_xor_sync(0xffffffffu, tm, 8));
            float mnew = fmaxf(m_i[i], tm);
            float sc = __expf(m_i[i] - mnew);
            m_i[i] = mnew;
            l_i[i] *= sc;
#pragma unroll
            for (int c = 0; c < 4; c++) acc[i][c] *= sc;
            float rs = 0.f;
#pragma unroll
            for (int j = 0; j < 4; j++) {
                s[i][j] = __expf(s[i][j] - mnew);
                rs += s[i][j];
            }
            rs += __shfl_xor_sync(0xffffffffu, rs, 1);
            rs += __shfl_xor_sync(0xffffffffu, rs, 2);
            rs += __shfl_xor_sync(0xffffffffu, rs, 4);
            rs += __shfl_xor_sync(0xffffffffu, rs, 8);
            l_i[i] += rs;
        }

        __syncthreads();   // done reading KPs as K

        // Stage P into KPs
#pragma unroll
        for (int i = 0; i < 4; i++)
#pragma unroll
            for (int j = 0; j < 4; j++)
                KPs[(ty * 4 + i) * ASTR + tx * 4 + j] = s[i][j];
        __syncthreads();

        // PV: acc[i][c] += P[row][j] * V[j][tx*4+c]
#pragma unroll 16
        for (int j = 0; j < BKT; j++) {
            float4 vv = *(const float4*)&Vs[j * ASTR + tx * 4];
#pragma unroll
            for (int i = 0; i < 4; i++) {
                float p = KPs[(ty * 4 + i) * ASTR + j];
                acc[i][0] += p * vv.x;
                acc[i][1] += p * vv.y;
                acc[i][2] += p * vv.z;
                acc[i][3] += p * vv.w;
            }
        }
        __syncthreads();   // before next tile overwrites KPs/Vs
    }

    // Epilogue: O[b, q0+row, h*64 + tx*4 .. +3] = acc / l
#pragma unroll
    for (int i = 0; i < 4; i++) {
        float inv = 1.0f / l_i[i];
        float4 o = make_float4(acc[i][0] * inv, acc[i][1] * inv,
                               acc[i][2] * inv, acc[i][3] * inv);
        float* op = O + (size_t)b * SEQ * DMODEL
                      + (size_t)(q0 + ty * 4 + i) * DMODEL + h * DK + tx * 4;
        *(float4*)op = o;
    }
}

// ---------------------------------------------------------------------------
// Launch
// ---------------------------------------------------------------------------
extern "C" void kernel_launch(void* const* d_in, const int* in_sizes, int n_in,
                              void* d_out, int out_size)
{
    const float* q   = (const float*)d_in[0];
    const float* k   = (const float*)d_in[1];
    const float* v   = (const float*)d_in[2];
    const int*   msk = (const int*)  d_in[3];
    const float* Wq  = (const float*)d_in[4];
    const float* bq  = (const float*)d_in[5];
    const float* Wk  = (const float*)d_in[6];
    const float* bk  = (const float*)d_in[7];
    const float* Wv  = (const float*)d_in[8];
    const float* bv  = (const float*)d_in[9];
    const float* Wo  = (const float*)d_in[10];
    const float* bo  = (const float*)d_in[11];
    float* out = (float*)d_out;

    float *gq, *gk, *gv, *go;
    cudaGetSymbolAddress((void**)&gq, g_Q);
    cudaGetSymbolAddress((void**)&gk, g_K);
    cudaGetSymbolAddress((void**)&gv, g_V);
    cudaGetSymbolAddress((void**)&go, g_O);

    const int smem_attn = 3 * BQ * ASTR * sizeof(float);   // 52224 B
    cudaFuncSetAttribute(attn_kernel, cudaFuncAttributeMaxDynamicSharedMemorySize,
                         smem_attn);

    dim3 ggrid(DMODEL / GBN, MROWS / GBM);   // (8, 32)
    gemm_bias_kernel<<<ggrid, 256>>>(q, Wq, bq, gq, MROWS, DMODEL, DMODEL);
    gemm_bias_kernel<<<ggrid, 256>>>(k, Wk, bk, gk, MROWS, DMODEL, DMODEL);
    gemm_bias_kernel<<<ggrid, 256>>>(v, Wv, bv, gv, MROWS, DMODEL, DMODEL);

    dim3 agrid(SEQ / BQ, BATCH * NHEAD);     // (32, 32)
    attn_kernel<<<agrid, 256, smem_attn>>>(gq, gk, gv, msk, go);

    gemm_bias_kernel<<<ggrid, 256>>>(go, Wo, bo, out, MROWS, DMODEL, DMODEL);
}

// round 3
// speedup vs baseline: 3.8163x; 3.8163x over previous
#include <cuda_runtime.h>
#include <cuda_bf16.h>
#include <cstdint>
#include <math.h>

// Problem constants
#define BATCH   2
#define SEQ     2048
#define DMODEL  1024
#define NHEAD   16
#define DK      64
#define MROWS   (BATCH * SEQ)      // 4096

// ---------------------------------------------------------------------------
// Scratch (allocation-free rule: __device__ globals), all bf16 hi/lo pairs
// ---------------------------------------------------------------------------
__device__ __nv_bfloat16 c_qh[MROWS * DMODEL], c_ql[MROWS * DMODEL];
__device__ __nv_bfloat16 c_kh[MROWS * DMODEL], c_kl[MROWS * DMODEL];
__device__ __nv_bfloat16 c_vh[MROWS * DMODEL], c_vl[MROWS * DMODEL];
__device__ __nv_bfloat16 w_qh[DMODEL * DMODEL], w_ql[DMODEL * DMODEL];
__device__ __nv_bfloat16 w_kh[DMODEL * DMODEL], w_kl[DMODEL * DMODEL];
__device__ __nv_bfloat16 w_vh[DMODEL * DMODEL], w_vl[DMODEL * DMODEL];
__device__ __nv_bfloat16 w_oh[DMODEL * DMODEL], w_ol[DMODEL * DMODEL];
__device__ __nv_bfloat16 p_Qh[MROWS * DMODEL], p_Ql[MROWS * DMODEL];
__device__ __nv_bfloat16 p_Kh[MROWS * DMODEL], p_Kl[MROWS * DMODEL];
__device__ __nv_bfloat16 p_Vh[MROWS * DMODEL], p_Vl[MROWS * DMODEL];
__device__ __nv_bfloat16 p_Oh[MROWS * DMODEL], p_Ol[MROWS * DMODEL];

// ---------------------------------------------------------------------------
// Helpers: smem addr, cp.async, ldmatrix, mma (all sm_80-era, safe at compute_103)
// ---------------------------------------------------------------------------
__device__ __forceinline__ uint32_t smem_u32(const void* p) {
    uint32_t a;
    asm("{ .reg .u64 t; cvta.to.shared.u64 t, %1; cvt.u32.u64 %0, t; }"
        : "=r"(a) : "l"(p));
    return a;
}

__device__ __forceinline__ void cp16(uint32_t saddr, const void* gaddr) {
    asm volatile("cp.async.cg.shared.global [%0], [%1], 16;"
                 :: "r"(saddr), "l"(gaddr));
}
#define CP_COMMIT() asm volatile("cp.async.commit_group;")
#define CP_WAIT(n)  asm volatile("cp.async.wait_group %0;" :: "n"(n))

__device__ __forceinline__ void ldsm_x4(uint32_t* r, uint32_t addr) {
    asm volatile("ldmatrix.sync.aligned.m8n8.x4.shared.b16 {%0,%1,%2,%3}, [%4];"
                 : "=r"(r[0]), "=r"(r[1]), "=r"(r[2]), "=r"(r[3]) : "r"(addr));
}
__device__ __forceinline__ void ldsm_x4_t(uint32_t* r, uint32_t addr) {
    asm volatile("ldmatrix.sync.aligned.m8n8.x4.trans.shared.b16 {%0,%1,%2,%3}, [%4];"
                 : "=r"(r[0]), "=r"(r[1]), "=r"(r[2]), "=r"(r[3]) : "r"(addr));
}

__device__ __forceinline__ void mma16816(float* c, const uint32_t* a, const uint32_t* b) {
    asm volatile(
        "mma.sync.aligned.m16n8k16.row.col.f32.bf16.bf16.f32 "
        "{%0,%1,%2,%3}, {%4,%5,%6,%7}, {%8,%9}, {%0,%1,%2,%3};"
        : "+f"(c[0]), "+f"(c[1]), "+f"(c[2]), "+f"(c[3])
        : "r"(a[0]), "r"(a[1]), "r"(a[2]), "r"(a[3]), "r"(b[0]), "r"(b[1]));
}

// split x,y into bf16 hi pair + bf16 lo (residual) pair, packed as bf16x2
__device__ __forceinline__ void split_pack(float x, float y, uint32_t& h, uint32_t& l) {
    __nv_bfloat16 hx = __float2bfloat16(x);
    __nv_bfloat16 hy = __float2bfloat16(y);
    __nv_bfloat16 lx = __float2bfloat16(x - __bfloat162float(hx));
    __nv_bfloat16 ly = __float2bfloat16(y - __bfloat162float(hy));
    h = ((uint32_t)__bfloat16_as_ushort(hy) << 16) | (uint32_t)__bfloat16_as_ushort(hx);
    l = ((uint32_t)__bfloat16_as_ushort(ly) << 16) | (uint32_t)__bfloat16_as_ushort(lx);
}

// ---------------------------------------------------------------------------
// split convert: fp32 -> bf16 hi/lo
// ---------------------------------------------------------------------------
__global__ __launch_bounds__(256)
void split_kernel(const float* __restrict__ src,
                  __nv_bfloat16* __restrict__ h,
                  __nv_bfloat16* __restrict__ l, int n)
{
    int i = (blockIdx.x * blockDim.x + threadIdx.x) * 4;
    if (i >= n) return;
    float4 v = *(const float4*)(src + i);
    uint32_t h0, h1, l0, l1;
    split_pack(v.x, v.y, h0, l0);
    split_pack(v.z, v.w, h1, l1);
    *(uint2*)(h + i) = make_uint2(h0, h1);
    *(uint2*)(l + i) = make_uint2(l0, l1);
}

// ---------------------------------------------------------------------------
// GEMM: C[M,N] = A[M,K] @ W[N,K]^T + bias, bf16x3 via mma.sync.
// CTA 128x128, 256 thr (8 warps, 4x2), warp tile 32x64, K-chunk 32.
// smem rows: 32 bf16 = 64B data, stride 80B (bank-shift 5 -> conflict-free ldmatrix).
// ---------------------------------------------------------------------------
#define GK      32
#define GSTR    80
#define GBUF    10240     // 128 rows * 80B
#define GSTAGE  40960     // Ah,Al,Wh,Wl

__device__ __forceinline__ void gemm_load_stage(
    uint32_t sbase, int tid, int kt, int row0, int col0, int K,
    const __nv_bfloat16* Ah, const __nv_bfloat16* Al,
    const __nv_bfloat16* Wh, const __nv_bfloat16* Wl)
{
    const int kc = kt * GK;
    const uint32_t st = sbase + (kt & 1) * GSTAGE;
#pragma unroll
    for (int u = 0; u < 2; u++) {
        int cid = tid + u * 256;          // 0..511
        int row = cid >> 2, g = cid & 3;
        uint32_t sa = st + row * GSTR + g * 16;
        size_t aoff = (size_t)(row0 + row) * K + kc + g * 8;
        size_t woff = (size_t)(col0 + row) * K + kc + g * 8;
        cp16(sa,            Ah + aoff);
        cp16(sa + GBUF,     Al + aoff);
        cp16(sa + 2 * GBUF, Wh + woff);
        cp16(sa + 3 * GBUF, Wl + woff);
    }
}

__device__ __forceinline__ void gemm_compute_stage(
    uint32_t sbase, int kt, int lane, int wm, int wn, float (&acc)[2][8][4])
{
    const uint32_t sb = sbase + (kt & 1) * GSTAGE;
    const int grp = lane >> 3, lq = lane & 7;
#pragma unroll
    for (int kk = 0; kk < 2; kk++) {
        uint32_t ahf[2][4], alf[2][4];
#pragma unroll
        for (int i = 0; i < 2; i++) {
            int row = wm * 32 + i * 16 + lq + (grp & 1) * 8;
            int g = 2 * kk + (grp >> 1);
            uint32_t ad = sb + row * GSTR + g * 16;
            ldsm_x4(ahf[i], ad);
            ldsm_x4(alf[i], ad + GBUF);
        }
#pragma unroll
        for (int jp = 0; jp < 4; jp++) {
            int j = 2 * jp + (grp >> 1);
            int g = 2 * kk + (grp & 1);
            int rowb = wn * 64 + 8 * j + lq;
            uint32_t bd = sb + 2 * GBUF + rowb * GSTR + g * 16;
            uint32_t bh[4], bl[4];
            ldsm_x4(bh, bd);
            ldsm_x4(bl, bd + GBUF);
#pragma unroll
            for (int i = 0; i < 2; i++) {
                mma16816(acc[i][2 * jp],     ahf[i], bh);
                mma16816(acc[i][2 * jp],     ahf[i], bl);
                mma16816(acc[i][2 * jp],     alf[i], bh);
                mma16816(acc[i][2 * jp + 1], ahf[i], bh + 2);
                mma16816(acc[i][2 * jp + 1], ahf[i], bl + 2);
                mma16816(acc[i][2 * jp + 1], alf[i], bh + 2);
            }
        }
    }
}

__global__ __launch_bounds__(256, 2)
void gemm_mma(const __nv_bfloat16* __restrict__ Ah, const __nv_bfloat16* __restrict__ Al,
              const __nv_bfloat16* __restrict__ Wh, const __nv_bfloat16* __restrict__ Wl,
              const float* __restrict__ bias,
              float* __restrict__ Cf,
              __nv_bfloat16* __restrict__ Ch, __nv_bfloat16* __restrict__ Cl,
              int M, int N, int K)
{
    extern __shared__ char smem[];
    const uint32_t sbase = smem_u32(smem);
    const int tid = threadIdx.x, lane = tid & 31, wid = tid >> 5;
    const int wm = wid & 3, wn = wid >> 2;
    const int row0 = blockIdx.y * 128, col0 = blockIdx.x * 128;

    float acc[2][8][4];
#pragma unroll
    for (int i = 0; i < 2; i++)
#pragma unroll
        for (int j = 0; j < 8; j++)
#pragma unroll
            for (int t = 0; t < 4; t++) acc[i][j][t] = 0.f;

    const int nch = K / GK;
    gemm_load_stage(sbase, tid, 0, row0, col0, K, Ah, Al, Wh, Wl);
    CP_COMMIT();

    for (int kt = 0; kt < nch; kt++) {
        if (kt + 1 < nch) {
            gemm_load_stage(sbase, tid, kt + 1, row0, col0, K, Ah, Al, Wh, Wl);
            CP_COMMIT();
            CP_WAIT(1);
        } else {
            CP_WAIT(0);
        }
        __syncthreads();
        gemm_compute_stage(sbase, kt, lane, wm, wn, acc);
        __syncthreads();
    }

    const int r = lane >> 2, cq = 2 * (lane & 3);
#pragma unroll
    for (int i = 0; i < 2; i++) {
#pragma unroll
        for (int j = 0; j < 8; j++) {
            int row = row0 + wm * 32 + i * 16 + r;
            int col = col0 + wn * 64 + 8 * j + cq;
            float b0 = bias[col], b1 = bias[col + 1];
            float x0 = acc[i][j][0] + b0, x1 = acc[i][j][1] + b1;
            float x2 = acc[i][j][2] + b0, x3 = acc[i][j][3] + b1;
            if (Cf) {
                *(float2*)(Cf + (size_t)row * N + col)       = make_float2(x0, x1);
                *(float2*)(Cf + (size_t)(row + 8) * N + col) = make_float2(x2, x3);
            } else {
                uint32_t hh, ll;
                split_pack(x0, x1, hh, ll);
                *(uint32_t*)(Ch + (size_t)row * N + col) = hh;
                *(uint32_t*)(Cl + (size_t)row * N + col) = ll;
                split_pack(x2, x3, hh, ll);
                *(uint32_t*)(Ch + (size_t)(row + 8) * N + col) = hh;
                *(uint32_t*)(Cl + (size_t)(row + 8) * N + col) = ll;
            }
        }
    }
}

// ---------------------------------------------------------------------------
// Flash attention with mma.sync (bf16x3 for QK^T and PV).
// CTA: one (b,h), 64 q-rows; 4 warps, each 16 q-rows. Key tile 64.
// smem rows: 64 bf16 = 128B data, stride 144B (bank-shift 1/row -> conflict-free).
// ---------------------------------------------------------------------------
#define ASTRB 144
#define ABUF  9216      // 64 * 144
#define AKV   36864     // Kh,Kl,Vh,Vl
#define AQOFF 0
#define AKV0  18432     // after Qh,Ql
#define NKT   (SEQ / 64)

__device__ __forceinline__ void attn_load_kv(
    uint32_t sbase, int tid, int kt, size_t rowb, int colh,
    const __nv_bfloat16* Kh, const __nv_bfloat16* Kl,
    const __nv_bfloat16* Vh, const __nv_bfloat16* Vl)
{
    const int k0 = kt * 64;
    const uint32_t st = sbase + AKV0 + (kt & 1) * AKV;
#pragma unroll
    for (int u = 0; u < 16; u++) {
        const int buf = u >> 2;          // compile-time per iteration
        int rem = (u & 3) * 128 + tid;   // 0..511
        int row = rem >> 3, g = rem & 7;
        const __nv_bfloat16* src =
            (buf == 0 ? Kh : buf == 1 ? Kl : buf == 2 ? Vh : Vl)
            + (rowb + k0 + row) * DMODEL + colh + g * 8;
        cp16(st + buf * ABUF + row * ASTRB + g * 16, src);
    }
}

__global__ __launch_bounds__(128, 2)
void attn_mma(const __nv_bfloat16* __restrict__ Qh, const __nv_bfloat16* __restrict__ Ql,
              const __nv_bfloat16* __restrict__ Kh, const __nv_bfloat16* __restrict__ Kl,
              const __nv_bfloat16* __restrict__ Vh, const __nv_bfloat16* __restrict__ Vl,
              const int* __restrict__ mask,
              __nv_bfloat16* __restrict__ Oh, __nv_bfloat16* __restrict__ Ol)
{
    extern __shared__ char smem[];
    const uint32_t sbase = smem_u32(smem);
    const int tid = threadIdx.x, lane = tid & 31, w = tid >> 5;
    const int bh_ = blockIdx.y, b = bh_ >> 4, h = bh_ & 15;
    const int q0 = blockIdx.x * 64;
    const size_t rowb = (size_t)b * SEQ;
    const int colh = h * DK;
    const int grp = lane >> 3, lq = lane & 7;
    const int r = lane >> 2, cq = 2 * (lane & 3);
    const float SCALE = 1.0f / 32.0f;

    // Q tile async load (group 0)
#pragma unroll
    for (int u = 0; u < 8; u++) {
        const int buf = u >> 2;          // 0: Qh, 1: Ql
        int rem = (u & 3) * 128 + tid;
        int row = rem >> 3, g = rem & 7;
        const __nv_bfloat16* src = (buf ? Ql : Qh)
            + (rowb + q0 + row) * DMODEL + colh + g * 8;
        cp16(sbase + AQOFF + buf * ABUF + row * ASTRB + g * 16, src);
    }
    CP_COMMIT();

    attn_load_kv(sbase, tid, 0, rowb, colh, Kh, Kl, Vh, Vl);
    CP_COMMIT();

    CP_WAIT(1);          // Q done (KV0 may be pending)
    __syncthreads();

    // Q fragments -> registers
    uint32_t qhf[4][4], qlf[4][4];
#pragma unroll
    for (int kk = 0; kk < 4; kk++) {
        int rowq = 16 * w + lq + (grp & 1) * 8;
        int g = 2 * kk + (grp >> 1);
        uint32_t ad = sbase + AQOFF + rowq * ASTRB + g * 16;
        ldsm_x4(qhf[kk], ad);
        ldsm_x4(qlf[kk], ad + ABUF);
    }

    float o[8][4];
#pragma unroll
    for (int j = 0; j < 8; j++)
#pragma unroll
        for (int t = 0; t < 4; t++) o[j][t] = 0.f;
    float mr0 = -1e30f, mr1 = -1e30f, lr0 = 0.f, lr1 = 0.f;

    const int* mb0 = mask + (size_t)b * SEQ * SEQ + (size_t)(q0 + 16 * w + r) * SEQ;
    const int* mb1 = mb0 + 8 * SEQ;

    for (int kt = 0; kt < NKT; kt++) {
        if (kt + 1 < NKT) {
            attn_load_kv(sbase, tid, kt + 1, rowb, colh, Kh, Kl, Vh, Vl);
            CP_COMMIT();
            CP_WAIT(1);
        } else {
            CP_WAIT(0);
        }
        __syncthreads();
        const uint32_t st = sbase + AKV0 + (kt & 1) * AKV;

        // ----- S = Q K^T (bf16x3) -----
        float c[8][4];
#pragma unroll
        for (int j = 0; j < 8; j++)
#pragma unroll
            for (int t = 0; t < 4; t++) c[j][t] = 0.f;

#pragma unroll
        for (int kk = 0; kk < 4; kk++) {
#pragma unroll
            for (int jp = 0; jp < 4; jp++) {
                int j = 2 * jp + (grp >> 1);
                int g = 2 * kk + (grp & 1);
                uint32_t kd = st + (8 * j + lq) * ASTRB + g * 16;
                uint32_t kbh[4], kbl[4];
                ldsm_x4(kbh, kd);
                ldsm_x4(kbl, kd + ABUF);
                mma16816(c[2 * jp],     qhf[kk], kbh);
                mma16816(c[2 * jp],     qhf[kk], kbl);
                mma16816(c[2 * jp],     qlf[kk], kbh);
                mma16816(c[2 * jp + 1], qhf[kk], kbh + 2);
                mma16816(c[2 * jp + 1], qhf[kk], kbl + 2);
                mma16816(c[2 * jp + 1], qlf[kk], kbh + 2);
            }
        }

        // ----- mask + scale -----
        const int k0 = kt * 64;
#pragma unroll
        for (int j = 0; j < 8; j++) {
            int2 mm0 = *(const int2*)(mb0 + k0 + 8 * j + cq);
            int2 mm1 = *(const int2*)(mb1 + k0 + 8 * j + cq);
            c[j][0] = mm0.x ? c[j][0] * SCALE : -1e9f;
            c[j][1] = mm0.y ? c[j][1] * SCALE : -1e9f;
            c[j][2] = mm1.x ? c[j][2] * SCALE : -1e9f;
            c[j][3] = mm1.y ? c[j][3] * SCALE : -1e9f;
        }

        // ----- online softmax (rows r and r+8) -----
        float mx0 = -1e30f, mx1 = -1e30f;
#pragma unroll
        for (int j = 0; j < 8; j++) {
            mx0 = fmaxf(mx0, fmaxf(c[j][0], c[j][1]));
            mx1 = fmaxf(mx1, fmaxf(c[j][2], c[j][3]));
        }
        mx0 = fmaxf(mx0, __shfl_xor_sync(0xffffffffu, mx0, 1));
        mx0 = fmaxf(mx0, __shfl_xor_sync(0xffffffffu, mx0, 2));
        mx1 = fmaxf(mx1, __shfl_xor_sync(0xffffffffu, mx1, 1));
        mx1 = fmaxf(mx1, __shfl_xor_sync(0xffffffffu, mx1, 2));
        float mn0 = fmaxf(mr0, mx0), mn1 = fmaxf(mr1, mx1);
        float f0 = __expf(mr0 - mn0), f1 = __expf(mr1 - mn1);
        mr0 = mn0; mr1 = mn1;
        float rs0 = 0.f, rs1 = 0.f;
#pragma unroll
        for (int j = 0; j < 8; j++) {
            c[j][0] = __expf(c[j][0] - mn0);
            c[j][1] = __expf(c[j][1] - mn0);
            c[j][2] = __expf(c[j][2] - mn1);
            c[j][3] = __expf(c[j][3] - mn1);
            rs0 += c[j][0] + c[j][1];
            rs1 += c[j][2] + c[j][3];
        }
        rs0 += __shfl_xor_sync(0xffffffffu, rs0, 1);
        rs0 += __shfl_xor_sync(0xffffffffu, rs0, 2);
        rs1 += __shfl_xor_sync(0xffffffffu, rs1, 1);
        rs1 += __shfl_xor_sync(0xffffffffu, rs1, 2);
        lr0 = lr0 * f0 + rs0;
        lr1 = lr1 * f1 + rs1;
#pragma unroll
        for (int j = 0; j < 8; j++) {
            o[j][0] *= f0; o[j][1] *= f0;
            o[j][2] *= f1; o[j][3] *= f1;
        }

        // ----- O += P V (bf16x3) -----
#pragma unroll
        for (int kkp = 0; kkp < 4; kkp++) {
            uint32_t ph[4], pl[4];
            split_pack(c[2 * kkp][0],     c[2 * kkp][1],     ph[0], pl[0]);
            split_pack(c[2 * kkp][2],     c[2 * kkp][3],     ph[1], pl[1]);
            split_pack(c[2 * kkp + 1][0], c[2 * kkp + 1][1], ph[2], pl[2]);
            split_pack(c[2 * kkp + 1][2], c[2 * kkp + 1][3], ph[3], pl[3]);
#pragma unroll
            for (int jdp = 0; jdp < 4; jdp++) {
                int rowv = 16 * kkp + lq + (grp & 1) * 8;
                int g = 2 * jdp + (grp >> 1);
                uint32_t vd = st + 2 * ABUF + rowv * ASTRB + g * 16;
                uint32_t vbh[4], vbl[4];
                ldsm_x4_t(vbh, vd);
                ldsm_x4_t(vbl, vd + ABUF);
                mma16816(o[2 * jdp],     ph, vbh);
                mma16816(o[2 * jdp],     ph, vbl);
                mma16816(o[2 * jdp],     pl, vbh);
                mma16816(o[2 * jdp + 1], ph, vbh + 2);
                mma16816(o[2 * jdp + 1], ph, vbl + 2);
                mma16816(o[2 * jdp + 1], pl, vbh + 2);
            }
        }
        __syncthreads();
    }

    // ----- epilogue: normalize + split store for O-projection -----
    float i0 = 1.f / lr0, i1 = 1.f / lr1;
    size_t ro0 = (rowb + q0 + 16 * w + r) * DMODEL + colh;
    size_t ro1 = ro0 + 8 * DMODEL;
#pragma unroll
    for (int jd = 0; jd < 8; jd++) {
        uint32_t hh, ll;
        split_pack(o[jd][0] * i0, o[jd][1] * i0, hh, ll);
        *(uint32_t*)(Oh + ro0 + 8 * jd + cq) = hh;
        *(uint32_t*)(Ol + ro0 + 8 * jd + cq) = ll;
        split_pack(o[jd][2] * i1, o[jd][3] * i1, hh, ll);
        *(uint32_t*)(Oh + ro1 + 8 * jd + cq) = hh;
        *(uint32_t*)(Ol + ro1 + 8 * jd + cq) = ll;
    }
}

// ---------------------------------------------------------------------------
// Launch
// ---------------------------------------------------------------------------
extern "C" void kernel_launch(void* const* d_in, const int* in_sizes, int n_in,
                              void* d_out, int out_size)
{
    const float* q   = (const float*)d_in[0];
    const float* k   = (const float*)d_in[1];
    const float* v   = (const float*)d_in[2];
    const int*   msk = (const int*)  d_in[3];
    const float* Wq  = (const float*)d_in[4];
    const float* bq  = (const float*)d_in[5];
    const float* Wk  = (const float*)d_in[6];
    const float* bk  = (const float*)d_in[7];
    const float* Wv  = (const float*)d_in[8];
    const float* bv  = (const float*)d_in[9];
    const float* Wo  = (const float*)d_in[10];
    const float* bo  = (const float*)d_in[11];
    float* out = (float*)d_out;

    __nv_bfloat16 *qh, *ql, *kh, *kl, *vh, *vl;
    __nv_bfloat16 *wqh, *wql, *wkh, *wkl, *wvh, *wvl, *woh, *wol;
    __nv_bfloat16 *Qh, *Ql, *Kh, *Kl, *Vh, *Vl, *Ohp, *Olp;
    cudaGetSymbolAddress((void**)&qh,  c_qh);  cudaGetSymbolAddress((void**)&ql,  c_ql);
    cudaGetSymbolAddress((void**)&kh,  c_kh);  cudaGetSymbolAddress((void**)&kl,  c_kl);
    cudaGetSymbolAddress((void**)&vh,  c_vh);  cudaGetSymbolAddress((void**)&vl,  c_vl);
    cudaGetSymbolAddress((void**)&wqh, w_qh);  cudaGetSymbolAddress((void**)&wql, w_ql);
    cudaGetSymbolAddress((void**)&wkh, w_kh);  cudaGetSymbolAddress((void**)&wkl, w_kl);
    cudaGetSymbolAddress((void**)&wvh, w_vh);  cudaGetSymbolAddress((void**)&wvl, w_vl);
    cudaGetSymbolAddress((void**)&woh, w_oh);  cudaGetSymbolAddress((void**)&wol, w_ol);
    cudaGetSymbolAddress((void**)&Qh,  p_Qh);  cudaGetSymbolAddress((void**)&Ql,  p_Ql);
    cudaGetSymbolAddress((void**)&Kh,  p_Kh);  cudaGetSymbolAddress((void**)&Kl,  p_Kl);
    cudaGetSymbolAddress((void**)&Vh,  p_Vh);  cudaGetSymbolAddress((void**)&Vl,  p_Vl);
    cudaGetSymbolAddress((void**)&Ohp, p_Oh);  cudaGetSymbolAddress((void**)&Olp, p_Ol);

    const int smem_gemm = 2 * GSTAGE;                 // 81920
    const int smem_attn = AKV0 + 2 * AKV;             // 92160
    cudaFuncSetAttribute(gemm_mma, cudaFuncAttributeMaxDynamicSharedMemorySize, smem_gemm);
    cudaFuncSetAttribute(attn_mma, cudaFuncAttributeMaxDynamicSharedMemorySize, smem_attn);

    const int n1 = MROWS * DMODEL;    // 4M
    const int n2 = DMODEL * DMODEL;   // 1M
    split_kernel<<<n1 / 1024, 256>>>(q, qh, ql, n1);
    split_kernel<<<n1 / 1024, 256>>>(k, kh, kl, n1);
    split_kernel<<<n1 / 1024, 256>>>(v, vh, vl, n1);
    split_kernel<<<n2 / 1024, 256>>>(Wq, wqh, wql, n2);
    split_kernel<<<n2 / 1024, 256>>>(Wk, wkh, wkl, n2);
    split_kernel<<<n2 / 1024, 256>>>(Wv, wvh, wvl, n2);
    split_kernel<<<n2 / 1024, 256>>>(Wo, woh, wol, n2);

    dim3 gg(DMODEL / 128, MROWS / 128);   // (8, 32)
    gemm_mma<<<gg, 256, smem_gemm>>>(qh, ql, wqh, wql, bq, nullptr, Qh, Ql,
                                     MROWS, DMODEL, DMODEL);
    gemm_mma<<<gg, 256, smem_gemm>>>(kh, kl, wkh, wkl, bk, nullptr, Kh, Kl,
                                     MROWS, DMODEL, DMODEL);
    gemm_mma<<<gg, 256, smem_gemm>>>(vh, vl, wvh, wvl, bv, nullptr, Vh, Vl,
                                     MROWS, DMODEL, DMODEL);

    dim3 ag(SEQ / 64, BATCH * NHEAD);     // (32, 32)
    attn_mma<<<ag, 128, smem_attn>>>(Qh, Ql, Kh, Kl, Vh, Vl, msk, Ohp, Olp);

    gemm_mma<<<gg, 256, smem_gemm>>>(Ohp, Olp, woh, wol, bo, out, nullptr, nullptr,
                                     MROWS, DMODEL, DMODEL);
}